// round 16
// baseline (speedup 1.0000x reference)
#include <cuda_runtime.h>
#include <cuda_fp16.h>
#include <cstdint>

// ---------------------------------------------------------------------------
// LinearAttention on GB300 (sm_103a via compute_103 PTX)
// Round 15: R13 resubmission with the real bug fixed — apply_attn's static
// shared (49.4KB) exceeded the 48KB static limit; now dynamic smem.
// Core kernels: 8x8 register tiles (LDS:FMA 1:16). GEMMs: R12 fused config.
// B=4, S=4096, D=1024, H=16, hd=64
// ---------------------------------------------------------------------------

#define BATCH 4
#define SEQ   4096
#define EMB   1024
#define HEADS 16
#define HDIM  64
#define ROWS  (BATCH * SEQ)     // 16384
#define BH    (BATCH * HEADS)   // 64
#define KVSP  8                 // s-splits (blocks); x4 subgroup partials
#define KVSR  (SEQ / KVSP)      // 512
#define KSPLITS (KVSP * 4)      // 32 partial sets
#define KVCH  32                // staged rows per chunk

// GEMM tiling (R8/R12 config — measured best)
#define MT 128
#define NTT 128
#define KC 32
#define KCH (EMB / KC)          // 32
#define STAGES 3
#define G_THREADS 256
#define PITCH16B 80
#define SZ_H16  (MT * PITCH16B)
#define OFF_AH  0
#define OFF_BH  (SZ_H16)
#define STAGE_BYTES (2 * SZ_H16)         // 20480
#define SMEM_DYN (STAGES * STAGE_BYTES)  // 61440 -> 2 CTAs/SM

// apply_attn dynamic smem: Qt[64][128] + KVs[64][64] + Ksums[64]
#define APPLY_SMEM ((64 * 128 + 64 * 64 + 64) * 4)   // 49408

// ---------------------------------------------------------------------------
// Scratch
// ---------------------------------------------------------------------------
__device__ __align__(256) float g_Q[(size_t)ROWS * EMB];
__device__ __align__(256) float g_K[(size_t)ROWS * EMB];
__device__ __align__(256) float g_V[(size_t)ROWS * EMB];
__device__ __align__(256) __half g_Xq[(size_t)ROWS * EMB];      // query fp16
__device__ __align__(256) __half g_Xh[(size_t)ROWS * EMB];      // keyv fp16 / attn out
__device__ __align__(256) __half g_Wh[4][(size_t)EMB * EMB];    // weights [n][k]
__device__ float g_KVp[(size_t)KSPLITS * BH * HDIM * HDIM];
__device__ float g_Ksump[(size_t)KSPLITS * BH * HDIM];
__device__ float g_KV[(size_t)BH * HDIM * HDIM];
__device__ float g_Ksum[(size_t)BH * HDIM];

// ---------------------------------------------------------------------------
// helpers
// ---------------------------------------------------------------------------
__device__ __forceinline__ uint32_t smem_u32(const void* p) {
    uint32_t a;
    asm("{ .reg .u64 t; cvta.to.shared.u64 t, %1; cvt.u32.u64 %0, t; }" : "=r"(a) : "l"(p));
    return a;
}
__device__ __forceinline__ void cp16(uint32_t saddr, const void* gaddr) {
    asm volatile("cp.async.cg.shared.global [%0], [%1], 16;" :: "r"(saddr), "l"(gaddr) : "memory");
}
__device__ __forceinline__ void ldsm4(uint32_t& r0, uint32_t& r1, uint32_t& r2,
                                      uint32_t& r3, uint32_t addr) {
    asm volatile("ldmatrix.sync.aligned.m8n8.x4.shared.b16 {%0,%1,%2,%3}, [%4];"
                 : "=r"(r0), "=r"(r1), "=r"(r2), "=r"(r3) : "r"(addr));
}
__device__ __forceinline__ void mma_f16(float* c, const uint32_t* a, const uint32_t* b) {
    asm volatile(
        "mma.sync.aligned.m16n8k16.row.col.f32.f16.f16.f32 "
        "{%0,%1,%2,%3}, {%4,%5,%6,%7}, {%8,%9}, {%0,%1,%2,%3};"
        : "+f"(c[0]), "+f"(c[1]), "+f"(c[2]), "+f"(c[3])
        : "r"(a[0]), "r"(a[1]), "r"(a[2]), "r"(a[3]), "r"(b[0]), "r"(b[1]));
}

// ---------------------------------------------------------------------------
// GEMM with per-CTA sub-GEMM select (R12). nsub=3: Q/K/V fused; nsub=1: O.
// ---------------------------------------------------------------------------
__global__ __launch_bounds__(G_THREADS, 2) void gemm_f16(
    const __half* __restrict__ A0, const __half* __restrict__ A1,
    const __half* __restrict__ Wbase,
    const float* __restrict__ b0, const float* __restrict__ b1,
    const float* __restrict__ b2,
    float* __restrict__ C0, float* __restrict__ C1, float* __restrict__ C2,
    int nsub)
{
    extern __shared__ char dsm[];
    const uint32_t dyn = smem_u32(dsm);

    const int tid  = threadIdx.x;
    const int wid  = tid >> 5;
    const int lane = tid & 31;
    const int sub  = (nsub == 3) ? (blockIdx.x >> 3) : 0;
    const int m0 = blockIdx.y * MT;
    const int n0 = (blockIdx.x & 7) * NTT;
    const int wm = (wid >> 2) * 64;
    const int wn = (wid & 3) * 32;

    const __half* A = (sub == 0) ? A0 : A1;
    const __half* B = Wbase + (size_t)sub * EMB * EMB;
    const float* bias = (sub == 0) ? b0 : (sub == 1) ? b1 : b2;
    float* C = (sub == 0) ? C0 : (sub == 1) ? C1 : C2;
    const int elu_mode = (nsub == 3) ? (sub < 2) : 0;

    auto load_stage = [&](int ch) {
        const uint32_t sb = dyn + (uint32_t)(ch % STAGES) * STAGE_BYTES;
        const int k0 = ch * KC;
        #pragma unroll
        for (int i = tid; i < 1024; i += G_THREADS) {
            const int half = i >> 9;
            const int rem  = i & 511;
            const int rr   = rem >> 2;
            const int g    = rem & 3;
            const __half* gp = half ? B : A;
            const int row = (half ? n0 : m0) + rr;
            cp16(sb + (uint32_t)half * SZ_H16 + (uint32_t)rr * PITCH16B + g * 16u,
                 gp + (size_t)row * EMB + k0 + g * 8);
        }
        asm volatile("cp.async.commit_group;" ::: "memory");
    };

    float acc[4][4][4];
    #pragma unroll
    for (int i = 0; i < 4; i++)
        #pragma unroll
        for (int j = 0; j < 4; j++)
            #pragma unroll
            for (int q = 0; q < 4; q++) acc[i][j][q] = 0.f;

    #pragma unroll
    for (int s = 0; s < STAGES - 1; s++) load_stage(s);

    for (int ch = 0; ch < KCH; ch++) {
        if (ch + STAGES - 1 < KCH) load_stage(ch + STAGES - 1);
        else asm volatile("cp.async.commit_group;" ::: "memory");
        asm volatile("cp.async.wait_group %0;" :: "n"(STAGES - 1) : "memory");
        __syncthreads();

        const uint32_t sb = dyn + (uint32_t)(ch % STAGES) * STAGE_BYTES;
        #pragma unroll
        for (int ks = 0; ks < 2; ks++) {
            const int kl = ks * 16;
            const int a_row = wm + (lane & 15);
            const int a_col = kl + (lane >> 4) * 8;
            const int b_row = wn + (lane & 7) + ((lane >> 4) & 1) * 8;
            const int b_col = kl + ((lane >> 3) & 1) * 8;

            uint32_t af[4][4];
            #pragma unroll
            for (int fm = 0; fm < 4; fm++) {
                uint32_t off = (uint32_t)(a_row + fm * 16) * PITCH16B + (uint32_t)a_col * 2u;
                ldsm4(af[fm][0], af[fm][1], af[fm][2], af[fm][3], sb + OFF_AH + off);
            }
            uint32_t bf[2][4];
            #pragma unroll
            for (int fp = 0; fp < 2; fp++) {
                uint32_t off = (uint32_t)(b_row + fp * 16) * PITCH16B + (uint32_t)b_col * 2u;
                ldsm4(bf[fp][0], bf[fp][1], bf[fp][2], bf[fp][3], sb + OFF_BH + off);
            }
            #pragma unroll
            for (int fm = 0; fm < 4; fm++)
                #pragma unroll
                for (int fn = 0; fn < 4; fn++)
                    mma_f16(acc[fm][fn], af[fm], &bf[fn >> 1][(fn & 1) * 2]);
        }
        __syncthreads();
    }

    const int er = lane >> 2;
    const int ec = (lane & 3) * 2;
    #pragma unroll
    for (int fn = 0; fn < 4; fn++) {
        const int col = n0 + wn + fn * 8 + ec;
        const float bb0 = bias[col], bb1 = bias[col + 1];
        #pragma unroll
        for (int fm = 0; fm < 4; fm++) {
            const int row = m0 + wm + fm * 16 + er;
            #pragma unroll
            for (int h = 0; h < 2; h++) {
                float v0 = acc[fm][fn][2 * h + 0] + bb0;
                float v1 = acc[fm][fn][2 * h + 1] + bb1;
                if (elu_mode) {
                    v0 = (v0 > 0.f) ? (v0 + 1.f) : __expf(v0);
                    v1 = (v1 > 0.f) ? (v1 + 1.f) : __expf(v1);
                }
                *(float2*)(C + (size_t)(row + 8 * h) * EMB + col) = make_float2(v0, v1);
            }
        }
    }
}

// ---------------------------------------------------------------------------
// fp32 -> fp16, two tensors in one launch
// ---------------------------------------------------------------------------
__global__ __launch_bounds__(256) void conv2_f16(
    const float* __restrict__ X0, const float* __restrict__ X1,
    __half* __restrict__ H0, __half* __restrict__ H1)
{
    const float* X = blockIdx.y ? X1 : X0;
    __half* H = blockIdx.y ? H1 : H0;
    size_t i = ((size_t)blockIdx.x * 256 + threadIdx.x) * 4;
    float4 v = *(const float4*)(X + i);
    ushort4 hv;
    hv.x = __half_as_ushort(__float2half_rn(v.x));
    hv.y = __half_as_ushort(__float2half_rn(v.y));
    hv.z = __half_as_ushort(__float2half_rn(v.z));
    hv.w = __half_as_ushort(__float2half_rn(v.w));
    *(ushort4*)(H + i) = hv;
}

// ---------------------------------------------------------------------------
// Weight transpose + fp16, all 4 weights in one launch
// ---------------------------------------------------------------------------
__global__ __launch_bounds__(256) void conv_w_all(
    const float* __restrict__ W0, const float* __restrict__ W1,
    const float* __restrict__ W2, const float* __restrict__ W3,
    __half* __restrict__ Hbase)
{
    __shared__ float tile[32][33];
    const int z = blockIdx.z;
    const float* W = (z == 0) ? W0 : (z == 1) ? W1 : (z == 2) ? W2 : W3;
    __half* H = Hbase + (size_t)z * EMB * EMB;
    const int n0 = blockIdx.x * 32, k0 = blockIdx.y * 32;
    const int tx = threadIdx.x & 31, ty = threadIdx.x >> 5;
    #pragma unroll
    for (int j = 0; j < 32; j += 8)
        tile[ty + j][tx] = W[(size_t)(k0 + ty + j) * EMB + n0 + tx];
    __syncthreads();
    #pragma unroll
    for (int j = 0; j < 32; j += 8)
        H[(size_t)(n0 + ty + j) * EMB + k0 + tx] = __float2half_rn(tile[tx][ty + j]);
}

// ---------------------------------------------------------------------------
// KV summarization: 8x8 register tiles, 4 s-subgroups x 64 threads.
// grid (BH, KVSP). Partials indexed (sp*4+g). Static smem 16KB (OK).
// ---------------------------------------------------------------------------
__global__ __launch_bounds__(256) void kv_partial()
{
    const int bh = blockIdx.x, sp = blockIdx.y;
    const int b = bh / HEADS, h = bh % HEADS;
    const int t = threadIdx.x;
    const int g = t >> 6;               // s-subgroup 0..3
    const int u = t & 63;
    const int d0 = (u & 7) * 8;
    const int e0 = (u >> 3) * 8;

    __shared__ float Ks[KVCH][HDIM];
    __shared__ float Vs[KVCH][HDIM];

    float acc[8][8];
    #pragma unroll
    for (int i = 0; i < 8; i++)
        #pragma unroll
        for (int j = 0; j < 8; j++) acc[i][j] = 0.f;
    float ksum[8];
    #pragma unroll
    for (int i = 0; i < 8; i++) ksum[i] = 0.f;

    const float* Kbase = g_K + (size_t)b * SEQ * EMB + h * HDIM;
    const float* Vbase = g_V + (size_t)b * SEQ * EMB + h * HDIM;

    const int s_begin = sp * KVSR;
    for (int s0 = s_begin; s0 < s_begin + KVSR; s0 += KVCH) {
        // stage 32 rows of K and V: 1024 float4, 4 per thread
        #pragma unroll
        for (int i = t; i < 1024; i += 256) {
            const int arr = i >> 9;
            const int rem = i & 511;
            const int rr = rem >> 4, cc = (rem & 15) * 4;
            const float* src = arr ? Vbase : Kbase;
            float* dst = arr ? &Vs[rr][cc] : &Ks[rr][cc];
            *(float4*)dst = *(const float4*)(src + (size_t)(s0 + rr) * EMB + cc);
        }
        __syncthreads();
        #pragma unroll
        for (int ss = 0; ss < 8; ss++) {
            const int row = g * 8 + ss;
            float kk[8], vv[8];
            *(float4*)&kk[0] = *(const float4*)&Ks[row][d0];
            *(float4*)&kk[4] = *(const float4*)&Ks[row][d0 + 4];
            *(float4*)&vv[0] = *(const float4*)&Vs[row][e0];
            *(float4*)&vv[4] = *(const float4*)&Vs[row][e0 + 4];
            #pragma unroll
            for (int i = 0; i < 8; i++) {
                ksum[i] += kk[i];
                #pragma unroll
                for (int j = 0; j < 8; j++)
                    acc[i][j] += kk[i] * vv[j];
            }
        }
        __syncthreads();
    }

    float* KVp = g_KVp + ((size_t)(sp * 4 + g) * BH + bh) * (HDIM * HDIM);
    #pragma unroll
    for (int i = 0; i < 8; i++) {
        *(float4*)(KVp + (size_t)(d0 + i) * HDIM + e0)     = *(float4*)&acc[i][0];
        *(float4*)(KVp + (size_t)(d0 + i) * HDIM + e0 + 4) = *(float4*)&acc[i][4];
    }
    if ((u >> 3) == 0) {
        float* Kp = g_Ksump + ((size_t)(sp * 4 + g) * BH + bh) * HDIM;
        #pragma unroll
        for (int i = 0; i < 8; i++) Kp[d0 + i] = ksum[i];
    }
}

__global__ __launch_bounds__(256) void kv_reduce()
{
    const int bh = blockIdx.x;
    const int t = threadIdx.x;
    for (int i = t; i < HDIM * HDIM; i += 256) {
        float s = 0.f;
        #pragma unroll
        for (int sp = 0; sp < KSPLITS; sp++)
            s += g_KVp[((size_t)sp * BH + bh) * (HDIM * HDIM) + i];
        g_KV[(size_t)bh * (HDIM * HDIM) + i] = s;
    }
    if (t < HDIM) {
        float s = 0.f;
        #pragma unroll
        for (int sp = 0; sp < KSPLITS; sp++)
            s += g_Ksump[((size_t)sp * BH + bh) * HDIM + t];
        g_Ksum[(size_t)bh * HDIM + t] = s;
    }
}

// ---------------------------------------------------------------------------
// Apply: 128-row tiles, 128 threads, 8x8 per thread; fp16 out into g_Xh.
// Dynamic smem (49408 B): Qt[64][128] | KVs[64][64] | Ksums[64].
// ---------------------------------------------------------------------------
__global__ __launch_bounds__(128) void apply_attn()
{
    extern __shared__ float asmem[];
    float* Qt    = asmem;                       // [d][row] : 64 x 128
    float* KVs   = asmem + 64 * 128;            // [d][e]   : 64 x 64
    float* Ksums = asmem + 64 * 128 + 64 * 64;  // [d]

    const int stile = blockIdx.x;
    const int bh = blockIdx.y;
    const int b = bh / HEADS, h = bh % HEADS;
    const int t = threadIdx.x;

    const int s0 = stile * 128;
    const float* Qbase = g_Q + (size_t)(b * SEQ + s0) * EMB + h * HDIM;

    for (int idx = t; idx < 128 * HDIM; idx += 128) {
        int rr = idx >> 6, cc = idx & 63;
        Qt[cc * 128 + rr] = Qbase[(size_t)rr * EMB + cc];
    }
    for (int idx = t; idx < HDIM * HDIM; idx += 128)
        KVs[idx] = g_KV[(size_t)bh * (HDIM * HDIM) + idx];
    if (t < HDIM) Ksums[t] = g_Ksum[(size_t)bh * HDIM + t];
    __syncthreads();

    const int r0 = (t & 15) * 8;
    const int e0 = (t >> 4) * 8;

    float acc[8][8];
    #pragma unroll
    for (int i = 0; i < 8; i++)
        #pragma unroll
        for (int j = 0; j < 8; j++) acc[i][j] = 0.f;
    float nrm[8];
    #pragma unroll
    for (int i = 0; i < 8; i++) nrm[i] = 0.f;

    #pragma unroll
    for (int dd = 0; dd < HDIM; dd++) {
        float qq[8], vv[8];
        *(float4*)&qq[0] = *(const float4*)&Qt[dd * 128 + r0];
        *(float4*)&qq[4] = *(const float4*)&Qt[dd * 128 + r0 + 4];
        *(float4*)&vv[0] = *(const float4*)&KVs[dd * 64 + e0];
        *(float4*)&vv[4] = *(const float4*)&KVs[dd * 64 + e0 + 4];
        const float ks = Ksums[dd];
        #pragma unroll
        for (int i = 0; i < 8; i++) {
            nrm[i] += qq[i] * ks;
            #pragma unroll
            for (int j = 0; j < 8; j++)
                acc[i][j] += qq[i] * vv[j];
        }
    }

    #pragma unroll
    for (int i = 0; i < 8; i++) {
        const float inv = 1.f / (nrm[i] + 1e-6f);
        size_t obase = (size_t)(b * SEQ + s0 + r0 + i) * EMB + h * HDIM + e0;
        ushort4 h0, h1;
        h0.x = __half_as_ushort(__float2half_rn(acc[i][0] * inv));
        h0.y = __half_as_ushort(__float2half_rn(acc[i][1] * inv));
        h0.z = __half_as_ushort(__float2half_rn(acc[i][2] * inv));
        h0.w = __half_as_ushort(__float2half_rn(acc[i][3] * inv));
        h1.x = __half_as_ushort(__float2half_rn(acc[i][4] * inv));
        h1.y = __half_as_ushort(__float2half_rn(acc[i][5] * inv));
        h1.z = __half_as_ushort(__float2half_rn(acc[i][6] * inv));
        h1.w = __half_as_ushort(__float2half_rn(acc[i][7] * inv));
        *(ushort4*)(g_Xh + obase)     = h0;
        *(ushort4*)(g_Xh + obase + 4) = h1;
    }
}

// ---------------------------------------------------------------------------
// Launch
// ---------------------------------------------------------------------------
extern "C" void kernel_launch(void* const* d_in, const int* in_sizes, int n_in,
                              void* d_out, int out_size)
{
    const float* query = (const float*)d_in[0];
    const float* keyv  = (const float*)d_in[1];
    const float* Wq = (const float*)d_in[2];
    const float* bq = (const float*)d_in[3];
    const float* Wk = (const float*)d_in[4];
    const float* bk = (const float*)d_in[5];
    const float* Wv = (const float*)d_in[6];
    const float* bv = (const float*)d_in[7];
    const float* Wo = (const float*)d_in[8];
    const float* bo = (const float*)d_in[9];
    float* out = (float*)d_out;

    float *pQ, *pK, *pV;
    __half *pXq, *pXh;
    __half (*pWh)[(size_t)EMB * EMB];
    cudaGetSymbolAddress((void**)&pQ, g_Q);
    cudaGetSymbolAddress((void**)&pK, g_K);
    cudaGetSymbolAddress((void**)&pV, g_V);
    cudaGetSymbolAddress((void**)&pXq, g_Xq);
    cudaGetSymbolAddress((void**)&pXh, g_Xh);
    cudaGetSymbolAddress((void**)&pWh, g_Wh);

    static bool attr_set = false;
    if (!attr_set) {
        cudaFuncSetAttribute(gemm_f16, cudaFuncAttributeMaxDynamicSharedMemorySize, SMEM_DYN);
        cudaFuncSetAttribute(apply_attn, cudaFuncAttributeMaxDynamicSharedMemorySize, APPLY_SMEM);
        attr_set = true;
    }

    const int conv_blocks = (int)(((size_t)ROWS * EMB / 4) / 256);  // 16384

    conv_w_all<<<dim3(EMB / 32, EMB / 32, 4), 256>>>(Wq, Wk, Wv, Wo, pWh[0]);
    conv2_f16<<<dim3(conv_blocks, 2), 256>>>(query, keyv, pXq, pXh);

    // Q/K/V projections fused (3072 CTAs)
    gemm_f16<<<dim3(24, ROWS / MT), G_THREADS, SMEM_DYN>>>(
        pXq, pXh, pWh[0], bq, bk, bv, pQ, pK, pV, 3);

    // Linear-attention core (fp32, 8x8 tiles)
    kv_partial<<<dim3(BH, KVSP), 256>>>();
    kv_reduce<<<BH, 256>>>();
    apply_attn<<<dim3(SEQ / 128, BH), 128, APPLY_SMEM>>>();   // fp16 into g_Xh

    // Output projection
    gemm_f16<<<dim3(8, ROWS / MT), G_THREADS, SMEM_DYN>>>(
        pXh, pXh, pWh[3], bo, bo, bo, out, out, out, 1);
}